// round 16
// baseline (speedup 1.0000x reference)
#include <cuda_runtime.h>
#include <cuda_fp16.h>
#include <cstdint>
#include <math.h>

#define TT 128
#define BB 256
#define HH 512
#define GG 2048
#define VV 128
#define LL 128
#define LDH (TT*BB)

typedef unsigned long long u64t;

__device__ __forceinline__ u64t pack2(float x, float y) {
    u64t r; asm("mov.b64 %0, {%1, %2};" : "=l"(r) : "f"(x), "f"(y)); return r;
}
__device__ __forceinline__ void fma2(u64t& d, u64t a, u64t b) {
    asm("fma.rn.f32x2 %0, %1, %2, %0;" : "+l"(d) : "l"(a), "l"(b));
}
__device__ __forceinline__ float2 unpack2(u64t v) {
    float2 r; asm("mov.b64 {%0, %1}, %2;" : "=f"(r.x), "=f"(r.y) : "l"(v)); return r;
}
__device__ __forceinline__ unsigned smem_u32(const void* p) {
    return (unsigned)__cvta_generic_to_shared(p);
}
#define CP16(dst, src) asm volatile("cp.async.ca.shared.global [%0], [%1], 16;" :: "r"(dst), "l"((const void*)(src)) : "memory")
#define CP_COMMIT      asm volatile("cp.async.commit_group;" ::: "memory")
#define CP_WAIT1       asm volatile("cp.async.wait_group 1;" ::: "memory")
#define CP_WAIT0       asm volatile("cp.async.wait_group 0;" ::: "memory")

__device__ __forceinline__ float ex2f(float x) { float r; asm("ex2.approx.ftz.f32 %0, %1;" : "=f"(r) : "f"(x)); return r; }
__device__ __forceinline__ float rcpf(float x) { float r; asm("rcp.approx.ftz.f32 %0, %1;" : "=f"(r) : "f"(x)); return r; }
__device__ __forceinline__ float sigf(float v)  { return rcpf(1.0f + ex2f(-1.4426950408889634f*v)); }
__device__ __forceinline__ float tanhf_(float v){ return 2.0f*rcpf(1.0f + ex2f(-2.8853900817779268f*v)) - 1.0f; }

__device__ __forceinline__ void split2h(float v, __half& h, __half& l) {
    h = __float2half(v);
    l = __float2half((v - __half2float(h)) * 2048.0f);
}

// ---------------- device scratch ----------------
__device__ __align__(16) float g_preF [TT*BB*GG];
__device__ __align__(16) float g_preB [TT*BB*GG];
__device__ __align__(16) float g_c0fT [HH*BB];
__device__ __align__(16) float g_c0bT [HH*BB];
__device__ __align__(16) float g_c1fT [HH*BB];
__device__ __align__(16) float g_c1bT [HH*BB];
__device__ __align__(16) float g_zeros[HH*BB];
__device__ __align__(16) float g_z    [BB*LL];
__device__ __align__(16) float g_y1fT [HH*BB];
__device__ __align__(16) float g_y1bT [HH*BB];
__device__ __align__(16) float g_dh1n [BB*HH];
__device__ __align__(16) float g_dc0  [BB*HH];
__device__ __align__(16) float g_dc1T [HH*BB];
__device__ __align__(16) float g_part0 [BB*GG];
__device__ __align__(16) float g_part1a[BB*GG];
__device__ __align__(16) float g_ptab [VV*GG];
__device__ __align__(16) float g_embT [HH*VV];
__device__ __align__(16) float g_wt   [1024*1024];
// fp16 splits
__device__ __align__(16) __half g_zh  [BB*HH];
__device__ __align__(16) __half g_a0h[LDH*HH],    g_a0l[LDH*HH];
__device__ __align__(16) __half g_a1h[LDH*2*HH],  g_a1l[LDH*2*HH];
__device__ __align__(16) __half g_y1sfh[LDH*HH],  g_y1sfl[LDH*HH];
__device__ __align__(16) __half g_y1sbh[LDH*HH],  g_y1sbl[LDH*HH];
__device__ __align__(16) __half g_w0h[2*GG*HH],   g_w0l[2*GG*HH];
__device__ __align__(16) __half g_w1h[2*GG*2*HH], g_w1l[2*GG*2*HH];
__device__ __align__(16) __half g_w4h[7*GG*HH],   g_w4l[7*GG*HH];
__device__ __align__(16) __half g_dh0h[BB*HH], g_dh0l[BB*HH];
__device__ __align__(16) __half g_dh1h[BB*HH], g_dh1l[BB*HH];

// ---------------- transforms ----------------
__global__ void wt_kernel(const float* __restrict__ in, float* __restrict__ out, int N, int K) {
    int total = N*K;
    for (int i = blockIdx.x*blockDim.x + threadIdx.x; i < total; i += gridDim.x*blockDim.x) {
        int n = i % N; int k = i / N;
        out[i] = in[(size_t)n*K + k];
    }
}
__global__ void wsplit2(const float* __restrict__ in, __half* __restrict__ oh,
                        __half* __restrict__ ol, int total) {
    for (int i = blockIdx.x*blockDim.x + threadIdx.x; i < total; i += gridDim.x*blockDim.x) {
        __half h, l; split2h(in[i], h, l);
        oh[i] = h; ol[i] = l;
    }
}
__global__ void wsplit4(const float* __restrict__ in, __half* __restrict__ oh,
                        __half* __restrict__ ol) {
    int total = GG*HH;
    for (int i = blockIdx.x*blockDim.x + threadIdx.x; i < total; i += gridDim.x*blockDim.x) {
        int j = i >> 9, k = i & 511;
        int n = j >> 2, g = j & 3;
        __half h, l; split2h(in[((size_t)(g*HH + n))*HH + k], h, l);
        oh[i] = h; ol[i] = l;
    }
}
__global__ void embsplit2(const int* __restrict__ x, const float* __restrict__ emb,
                          __half* __restrict__ ah, __half* __restrict__ al) {
    int total = LDH*HH;
    for (int i = blockIdx.x*blockDim.x + threadIdx.x; i < total; i += gridDim.x*blockDim.x) {
        int m = i >> 9, k = i & 511;
        int t = m / BB, b = m % BB;
        __half h, l; split2h(emb[x[b*TT + t]*HH + k], h, l);
        ah[i] = h; al[i] = l;
    }
}

// ============ HMMA pre-GEMM (round-14, unchanged) ============
#define HM_STAGE 30720u
#define MMA16816(c, a0,a1,a2,a3, b0,b1) \
  asm volatile("mma.sync.aligned.m16n8k16.row.col.f32.f16.f16.f32 " \
    "{%0,%1,%2,%3}, {%4,%5,%6,%7}, {%8,%9}, {%0,%1,%2,%3};" \
    : "+f"((c)[0]), "+f"((c)[1]), "+f"((c)[2]), "+f"((c)[3]) \
    : "r"(a0),"r"(a1),"r"(a2),"r"(a3),"r"(b0),"r"(b1))

__global__ __launch_bounds__(256, 2) void mma_hm(
    const __half* __restrict__ Ah, const __half* __restrict__ Al,
    const __half* __restrict__ Wh, const __half* __restrict__ Wl,
    const float* __restrict__ bias, float* __restrict__ C, int N, int K) {
    extern __shared__ __align__(16) char HSm[];
    unsigned sb = smem_u32(HSm);
    const int tid = threadIdx.x;
    const int lane = tid & 31;
    const int wid = tid >> 5;
    const int wmB = (wid & 3) * 32;
    const int wnB = (wid >> 2) * 32;
    const int bm = blockIdx.y * 128;
    const int bn = blockIdx.x * 64;
    const int NS = K / 32;

    const __half* Asrc[2] = { Ah + (size_t)bm*K, Al + (size_t)bm*K };
    const __half* Wsrc[2] = { Wh + (size_t)bn*K, Wl + (size_t)bn*K };

    #define HLOAD(s) { unsigned db_ = sb + (unsigned)((s)&1)*HM_STAGE; size_t kb_ = (size_t)(s)*32; \
        _Pragma("unroll") for (int j = 0; j < 4; j++) { \
            int c_ = tid + j*256; int mt_ = c_ >> 9; int rk_ = c_ & 511; \
            int r_ = rk_ >> 2; int o_ = (rk_ & 3) * 8; \
            CP16(db_ + (unsigned)(mt_*10240 + r_*80 + o_*2), Asrc[mt_] + (size_t)r_*K + kb_ + o_); } \
        _Pragma("unroll") for (int j = 0; j < 2; j++) { \
            int c_ = tid + j*256; int mt_ = c_ >> 8; int rk_ = c_ & 255; \
            int r_ = rk_ >> 2; int o_ = (rk_ & 3) * 8; \
            CP16(db_ + (unsigned)(20480 + mt_*5120 + r_*80 + o_*2), Wsrc[mt_] + (size_t)r_*K + kb_ + o_); } \
        CP_COMMIT; }

    float c0[2][4][4], c1[2][4][4];
    #pragma unroll
    for (int mt = 0; mt < 2; mt++)
        #pragma unroll
        for (int nt = 0; nt < 4; nt++)
            #pragma unroll
            for (int q = 0; q < 4; q++) { c0[mt][nt][q] = 0.0f; c1[mt][nt][q] = 0.0f; }

    HLOAD(0); HLOAD(1);
    CP_WAIT1; __syncthreads();

    const int arow = lane >> 2;
    const int acol = (lane & 3) * 2;

    for (int s = 0; s < NS; s++) {
        const char* bufb = HSm + (s & 1)*HM_STAGE;
        #pragma unroll
        for (int kk = 0; kk < 32; kk += 16) {
            uint32_t BH[4][2], BL[4][2];
            #pragma unroll
            for (int nt = 0; nt < 4; nt++) {
                const char* wb = bufb + 20480 + (wnB + nt*8 + arow)*80 + (acol + kk)*2;
                BH[nt][0] = *(const uint32_t*)wb;
                BH[nt][1] = *(const uint32_t*)(wb + 16);
                BL[nt][0] = *(const uint32_t*)(wb + 5120);
                BL[nt][1] = *(const uint32_t*)(wb + 5120 + 16);
            }
            #pragma unroll
            for (int mt = 0; mt < 2; mt++) {
                const char* ab = bufb + (wmB + mt*16 + arow)*80 + (acol + kk)*2;
                uint32_t AH0 = *(const uint32_t*)ab;
                uint32_t AH1 = *(const uint32_t*)(ab + 640);
                uint32_t AH2 = *(const uint32_t*)(ab + 16);
                uint32_t AH3 = *(const uint32_t*)(ab + 640 + 16);
                uint32_t AL0 = *(const uint32_t*)(ab + 10240);
                uint32_t AL1 = *(const uint32_t*)(ab + 10240 + 640);
                uint32_t AL2 = *(const uint32_t*)(ab + 10240 + 16);
                uint32_t AL3 = *(const uint32_t*)(ab + 10240 + 640 + 16);
                #pragma unroll
                for (int nt = 0; nt < 4; nt++) {
                    MMA16816(c0[mt][nt], AH0,AH1,AH2,AH3, BH[nt][0],BH[nt][1]);
                    MMA16816(c1[mt][nt], AH0,AH1,AH2,AH3, BL[nt][0],BL[nt][1]);
                    MMA16816(c1[mt][nt], AL0,AL1,AL2,AL3, BH[nt][0],BH[nt][1]);
                }
            }
        }
        if (s == NS - 1) break;
        __syncthreads();
        if (s + 2 < NS) { HLOAD(s+2); CP_WAIT1; }
        else            { CP_WAIT0; }
        __syncthreads();
    }

    const float INV = 4.8828125e-4f;
    #pragma unroll
    for (int mt = 0; mt < 2; mt++) {
        #pragma unroll
        for (int nt = 0; nt < 4; nt++) {
            int m0 = bm + wmB + mt*16 + arow;
            int n0 = bn + wnB + nt*8 + acol;
            float b0v = bias[n0], b1v = bias[n0+1];
            float2 o0 = make_float2(c0[mt][nt][0] + c1[mt][nt][0]*INV + b0v,
                                    c0[mt][nt][1] + c1[mt][nt][1]*INV + b1v);
            float2 o1 = make_float2(c0[mt][nt][2] + c1[mt][nt][2]*INV + b0v,
                                    c0[mt][nt][3] + c1[mt][nt][3]*INV + b1v);
            *(float2*)&C[(size_t)m0*N + n0]     = o0;
            *(float2*)&C[(size_t)(m0+8)*N + n0] = o1;
        }
    }
    #undef HLOAD
}

// ============ HMMA recurrent core: 64 b x 64 j, K=512, 2 blocks/SM ============
// Stage: Ah 5120 | Al 5120 | Wh 5120 | Wl 5120 = 20480 B; double-buffered = 40960 B.
#define GM_STAGE 20480u
#define GM_SMEM  (2*GM_STAGE)     // 40960 B (also covers Sg 64*66*4=16896)

__device__ __forceinline__ void hm_core(const __half* __restrict__ Ah,
                                        const __half* __restrict__ Al, int lda,
                                        const __half* __restrict__ Wh,
                                        const __half* __restrict__ Wl,
                                        int bm, int bn, char* HSm, float* Sg) {
    unsigned sb = smem_u32(HSm);
    const int tid = threadIdx.x;
    const int lane = tid & 31;
    const int wid = tid >> 5;
    const int wmB = (wid & 1) * 32;       // 2 m-groups of 32
    const int wnB = (wid >> 1) * 16;      // 4 n-groups of 16
    const __half* Asrc[2] = { Ah + (size_t)bm*lda, Al + (size_t)bm*lda };
    const __half* Wsrc[2] = { Wh + (size_t)bn*HH, Wl + (size_t)bn*HH };

    #define GLOAD(s) { unsigned db_ = sb + (unsigned)((s)&1)*GM_STAGE; size_t kb_ = (size_t)(s)*32; \
        _Pragma("unroll") for (int j = 0; j < 4; j++) { \
            int c_ = tid + j*256; \
            if (c_ < 512) { int mt_ = c_ >> 8; int rk_ = c_ & 255; \
                int r_ = rk_ >> 2; int o_ = (rk_ & 3) * 8; \
                CP16(db_ + (unsigned)(mt_*5120 + r_*80 + o_*2), Asrc[mt_] + (size_t)r_*lda + kb_ + o_); } \
            else { int c2_ = c_ - 512; int mt_ = c2_ >> 8; int rk_ = c2_ & 255; \
                int r_ = rk_ >> 2; int o_ = (rk_ & 3) * 8; \
                CP16(db_ + (unsigned)(10240 + mt_*5120 + r_*80 + o_*2), Wsrc[mt_] + (size_t)r_*HH + kb_ + o_); } } \
        CP_COMMIT; }

    float c0[2][2][4], c1[2][2][4];
    #pragma unroll
    for (int mt = 0; mt < 2; mt++)
        #pragma unroll
        for (int nt = 0; nt < 2; nt++)
            #pragma unroll
            for (int q = 0; q < 4; q++) { c0[mt][nt][q] = 0.0f; c1[mt][nt][q] = 0.0f; }

    GLOAD(0); GLOAD(1);
    CP_WAIT1; __syncthreads();

    const int arow = lane >> 2;
    const int acol = (lane & 3) * 2;

    for (int s = 0; s < 16; s++) {
        const char* bufb = HSm + (s & 1)*GM_STAGE;
        #pragma unroll
        for (int kk = 0; kk < 32; kk += 16) {
            uint32_t BH[2][2], BL[2][2];
            #pragma unroll
            for (int nt = 0; nt < 2; nt++) {
                const char* wb = bufb + 10240 + (wnB + nt*8 + arow)*80 + (acol + kk)*2;
                BH[nt][0] = *(const uint32_t*)wb;
                BH[nt][1] = *(const uint32_t*)(wb + 16);
                BL[nt][0] = *(const uint32_t*)(wb + 5120);
                BL[nt][1] = *(const uint32_t*)(wb + 5120 + 16);
            }
            #pragma unroll
            for (int mt = 0; mt < 2; mt++) {
                const char* ab = bufb + (wmB + mt*16 + arow)*80 + (acol + kk)*2;
                uint32_t AH0 = *(const uint32_t*)ab;
                uint32_t AH1 = *(const uint32_t*)(ab + 640);
                uint32_t AH2 = *(const uint32_t*)(ab + 16);
                uint32_t AH3 = *(const uint32_t*)(ab + 640 + 16);
                uint32_t AL0 = *(const uint32_t*)(ab + 5120);
                uint32_t AL1 = *(const uint32_t*)(ab + 5120 + 640);
                uint32_t AL2 = *(const uint32_t*)(ab + 5120 + 16);
                uint32_t AL3 = *(const uint32_t*)(ab + 5120 + 640 + 16);
                #pragma unroll
                for (int nt = 0; nt < 2; nt++) {
                    MMA16816(c0[mt][nt], AH0,AH1,AH2,AH3, BH[nt][0],BH[nt][1]);
                    MMA16816(c1[mt][nt], AH0,AH1,AH2,AH3, BL[nt][0],BL[nt][1]);
                    MMA16816(c1[mt][nt], AL0,AL1,AL2,AL3, BH[nt][0],BH[nt][1]);
                }
            }
        }
        if (s == 15) break;
        __syncthreads();
        if (s + 2 < 16) { GLOAD(s+2); CP_WAIT1; }
        else            { CP_WAIT0; }
        __syncthreads();
    }
    #undef GLOAD

    __syncthreads();
    const float INV = 4.8828125e-4f;
    #pragma unroll
    for (int mt = 0; mt < 2; mt++) {
        #pragma unroll
        for (int nt = 0; nt < 2; nt++) {
            int r0 = wmB + mt*16 + arow;
            int cc = wnB + nt*8 + acol;
            Sg[r0*66 + cc]       = c0[mt][nt][0] + c1[mt][nt][0]*INV;
            Sg[r0*66 + cc + 1]   = c0[mt][nt][1] + c1[mt][nt][1]*INV;
            Sg[(r0+8)*66 + cc]   = c0[mt][nt][2] + c1[mt][nt][2]*INV;
            Sg[(r0+8)*66 + cc+1] = c0[mt][nt][3] + c1[mt][nt][3]*INV;
        }
    }
    __syncthreads();
}

struct EpiT {
    const float* pre;
    const float* cinT; float* coutT;
    float* houtT;
    float* houtN;
    __half *osh, *osl; int olda;
};
// 64 rows x 16 n, 256 threads x 4 elems
__device__ __forceinline__ void hm_lstm_epi(const float* Sg, int bm, int n0, EpiT e) {
    const int tid = threadIdx.x;
    #pragma unroll
    for (int j = 0; j < 4; j++) {
        int idx = tid + j*256;
        int bl = idx >> 4, nn = idx & 15;
        int bg = bm + bl, n = n0 + nn;
        const float* g4 = Sg + bl*66 + nn*4;
        const float* pb = e.pre + (size_t)bg*GG;
        float gi = g4[0] + pb[n];
        float gf = g4[1] + pb[HH + n];
        float gg = g4[2] + pb[2*HH + n];
        float go = g4[3] + pb[3*HH + n];
        float cv = e.cinT[(size_t)n*BB + bg];
        float cn = sigf(gf)*cv + sigf(gi)*tanhf_(gg);
        e.coutT[(size_t)n*BB + bg] = cn;
        float hv = sigf(go)*tanhf_(cn);
        if (e.houtT) e.houtT[(size_t)n*BB + bg] = hv;
        if (e.houtN) e.houtN[(size_t)bg*HH + n] = hv;
        __half hh, hl; split2h(hv, hh, hl);
        e.osh[(size_t)bg*e.olda + n] = hh;
        e.osl[(size_t)bg*e.olda + n] = hl;
    }
}
__device__ __forceinline__ void hm_part_epi(const float* Sg, int bm, int n0,
                                            const float* __restrict__ bias,
                                            float* __restrict__ outp) {
    const int tid = threadIdx.x;
    #pragma unroll
    for (int j = 0; j < 4; j++) {
        int idx = tid + j*256;
        int bl = idx >> 4, nn = idx & 15;
        int bg = bm + bl, n = n0 + nn;
        const float* g4 = Sg + bl*66 + nn*4;
        float* ob = outp + (size_t)bg*GG;
        ob[n]        = g4[0] + bias[n];
        ob[HH + n]   = g4[1] + bias[HH + n];
        ob[2*HH + n] = g4[2] + bias[2*HH + n];
        ob[3*HH + n] = g4[3] + bias[3*HH + n];
    }
}

// ---------------- encoder recurrent step (both dirs via grid.z) ----------------
struct EStep {
    const __half *ah, *al; int alda;
    const __half *wh, *wl;
    const float* pre;
    const float* cinT; float* coutT;
    float* houtT;
    __half *osh, *osl; int olda;
};
__global__ __launch_bounds__(256, 2) void enc_step_hm(EStep D0, EStep D1) {
    extern __shared__ __align__(16) char HSm[];
    EStep d = blockIdx.z ? D1 : D0;
    int bm = blockIdx.y * 64, bn = blockIdx.x * 64;
    float* Sg = (float*)HSm;
    hm_core(d.ah, d.al, d.alda, d.wh, d.wl, bm, bn, HSm, Sg);
    EpiT e = { d.pre, d.cinT, d.coutT, d.houtT, nullptr, d.osh, d.osl, d.olda };
    hm_lstm_epi(Sg, bm, blockIdx.x*16, e);
}

// ---------------- decoder partial (init) ----------------
__global__ __launch_bounds__(256, 2) void dec_part_hm(
    const __half* __restrict__ ah, const __half* __restrict__ al,
    const __half* __restrict__ wh, const __half* __restrict__ wl,
    const float* __restrict__ bias, float* __restrict__ outp) {
    extern __shared__ __align__(16) char HSm[];
    int bm = blockIdx.y * 64, bn = blockIdx.x * 64;
    float* Sg = (float*)HSm;
    hm_core(ah, al, HH, wh, wl, bm, bn, HSm, Sg);
    hm_part_epi(Sg, bm, blockIdx.x*16, bias, outp);
}

// ---------------- decoder phase Y: cell1 (z=0) || part0' (z=1) ----------------
__global__ __launch_bounds__(256, 2) void dec_Y_hm(
    const __half* __restrict__ dh0h, const __half* __restrict__ dh0l,
    const __half* __restrict__ wih1h, const __half* __restrict__ wih1l,
    const float* __restrict__ part1a, float* __restrict__ dc1T,
    float* __restrict__ dh1n, __half* __restrict__ dh1h, __half* __restrict__ dh1l,
    const __half* __restrict__ whh0h, const __half* __restrict__ whh0l,
    const float* __restrict__ zerob, float* __restrict__ part0) {
    extern __shared__ __align__(16) char HSm[];
    int bm = blockIdx.y * 64, bn = blockIdx.x * 64;
    float* Sg = (float*)HSm;
    if (blockIdx.z == 0) {
        hm_core(dh0h, dh0l, HH, wih1h, wih1l, bm, bn, HSm, Sg);
        EpiT e = { part1a, dc1T, dc1T, nullptr, dh1n, dh1h, dh1l, HH };
        hm_lstm_epi(Sg, bm, blockIdx.x*16, e);
    } else {
        hm_core(dh0h, dh0l, HH, whh0h, whh0l, bm, bn, HSm, Sg);
        hm_part_epi(Sg, bm, blockIdx.x*16, zerob, part0);
    }
}

// ---- decoder phase Z: logits+argmax+cell0 (z=0) || part1a' (z=1) ----
__global__ __launch_bounds__(256, 2) void dec_Z_hm(
    const __half* __restrict__ dh1h, const __half* __restrict__ dh1l,
    const __half* __restrict__ whh1h, const __half* __restrict__ whh1l,
    const float* __restrict__ b1, float* __restrict__ part1a,
    const float* __restrict__ dh1n, const float* __restrict__ Wout,
    const float* __restrict__ bout,
    const float* __restrict__ Ptab, const float* __restrict__ part0,
    float* __restrict__ dc0, __half* __restrict__ dh0h, __half* __restrict__ dh0l,
    float* __restrict__ recon, int t) {
    extern __shared__ __align__(16) char HSm[];
    if (blockIdx.z == 1) {
        int bm = blockIdx.y * 64, bn = blockIdx.x * 64;
        float* Sg = (float*)HSm;
        hm_core(dh1h, dh1l, HH, whh1h, whh1l, bm, bn, HSm, Sg);
        hm_part_epi(Sg, bm, blockIdx.x*16, b1, part1a);
        return;
    }
    // logits role: 128 blocks x 256 threads, 2 batch rows each
    const int tid = threadIdx.x;
    const int bid = blockIdx.y*32 + blockIdx.x;   // 0..127
    const int b0r = bid * 2;
    float* sh = (float*)HSm;           // 2*512
    float* sv = sh + 2*HH;             // 2*128
    int*   si = (int*)(sv + 2*VV);     // 2*128
    ((float4*)sh)[tid] = ((const float4*)(dh1n + (size_t)b0r*HH))[tid];
    __syncthreads();
    const int v = tid & 127;
    const int r = tid >> 7;            // 0 or 1
    const float4* w4 = (const float4*)(Wout + (size_t)v*HH);
    float acc = bout[v];
    const float* s0 = sh + r*HH;
    #pragma unroll 8
    for (int k = 0; k < HH/4; k++) {
        float4 wv = w4[k];
        float4 a4 = *(const float4*)&s0[k*4];
        acc += a4.x*wv.x + a4.y*wv.y + a4.z*wv.z + a4.w*wv.w;
    }
    recon[(size_t)(b0r+r)*TT*VV + (size_t)t*VV + v] = acc;
    sv[r*VV + v] = acc;
    si[r*VV + v] = v;
    __syncthreads();
    for (int s2 = 64; s2 > 0; s2 >>= 1) {
        if (v < s2) {
            float ov = sv[r*VV + v + s2]; int oi = si[r*VV + v + s2];
            if (ov > sv[r*VV + v] || (ov == sv[r*VV + v] && oi < si[r*VV + v])) {
                sv[r*VV + v] = ov; si[r*VV + v] = oi;
            }
        }
        __syncthreads();
    }
    const int tk = si[r*VV];
    const int b = b0r + r;
    const int h0c = v * 4;
    const float* pt = Ptab + (size_t)tk*GG;
    const float* p0 = part0 + (size_t)b*GG;
    float4 pi = *(const float4*)&pt[0*HH + h0c]; float4 qi = *(const float4*)&p0[0*HH + h0c];
    float4 pf = *(const float4*)&pt[1*HH + h0c]; float4 qf = *(const float4*)&p0[1*HH + h0c];
    float4 pg = *(const float4*)&pt[2*HH + h0c]; float4 qg = *(const float4*)&p0[2*HH + h0c];
    float4 po = *(const float4*)&pt[3*HH + h0c]; float4 qo = *(const float4*)&p0[3*HH + h0c];
    float4 c4 = *(const float4*)&dc0[(size_t)b*HH + h0c];
    float gi[4] = {pi.x+qi.x, pi.y+qi.y, pi.z+qi.z, pi.w+qi.w};
    float gf[4] = {pf.x+qf.x, pf.y+qf.y, pf.z+qf.z, pf.w+qf.w};
    float gg[4] = {pg.x+qg.x, pg.y+qg.y, pg.z+qg.z, pg.w+qg.w};
    float go[4] = {po.x+qo.x, po.y+qo.y, po.z+qo.z, po.w+qo.w};
    float cc[4] = {c4.x, c4.y, c4.z, c4.w};
    float co[4];
    #pragma unroll
    for (int jj = 0; jj < 4; jj++) {
        float cn = sigf(gf[jj])*cc[jj] + sigf(gi[jj])*tanhf_(gg[jj]);
        co[jj] = cn;
        float hv = sigf(go[jj])*tanhf_(cn);
        __half hh, hl; split2h(hv, hh, hl);
        dh0h[(size_t)b*HH + h0c + jj] = hh;
        dh0l[(size_t)b*HH + h0c + jj] = hl;
    }
    *(float4*)&dc0[(size_t)b*HH + h0c] = make_float4(co[0], co[1], co[2], co[3]);
}

// ---------------- cell0 at t=0 (token fixed = 1) ----------------
__global__ __launch_bounds__(128) void cell0_init_kernel(const float* __restrict__ Ptab,
                                                         const float* __restrict__ part0,
                                                         float* __restrict__ dc0,
                                                         __half* __restrict__ dh0h,
                                                         __half* __restrict__ dh0l) {
    const int b = blockIdx.x;
    const int h0c = threadIdx.x * 4;
    const float* pt = Ptab + (size_t)1*GG;
    const float* p0 = part0 + (size_t)b*GG;
    float4 pi = *(const float4*)&pt[0*HH + h0c]; float4 qi = *(const float4*)&p0[0*HH + h0c];
    float4 pf = *(const float4*)&pt[1*HH + h0c]; float4 qf = *(const float4*)&p0[1*HH + h0c];
    float4 pg = *(const float4*)&pt[2*HH + h0c]; float4 qg = *(const float4*)&p0[2*HH + h0c];
    float4 po = *(const float4*)&pt[3*HH + h0c]; float4 qo = *(const float4*)&p0[3*HH + h0c];
    float4 c4 = *(const float4*)&dc0[(size_t)b*HH + h0c];
    float gi[4] = {pi.x+qi.x, pi.y+qi.y, pi.z+qi.z, pi.w+qi.w};
    float gf[4] = {pf.x+qf.x, pf.y+qf.y, pf.z+qf.z, pf.w+qf.w};
    float gg[4] = {pg.x+qg.x, pg.y+qg.y, pg.z+qg.z, pg.w+qg.w};
    float go[4] = {po.x+qo.x, po.y+qo.y, po.z+qo.z, po.w+qo.w};
    float cc[4] = {c4.x, c4.y, c4.z, c4.w};
    float co[4];
    #pragma unroll
    for (int j = 0; j < 4; j++) {
        float cn = sigf(gf[j])*cc[j] + sigf(gi[j])*tanhf_(gg[j]);
        co[j] = cn;
        float hv = sigf(go[j])*tanhf_(cn);
        __half hh, hl; split2h(hv, hh, hl);
        dh0h[(size_t)b*HH + h0c + j] = hh;
        dh0l[(size_t)b*HH + h0c + j] = hl;
    }
    *(float4*)&dc0[(size_t)b*HH + h0c] = make_float4(co[0], co[1], co[2], co[3]);
}

// ---------------- mu/logvar heads ([n][BB] inputs) ----------------
__global__ __launch_bounds__(256) void head_kernel(const float* __restrict__ hfT,
                                                   const float* __restrict__ hbT,
                                                   const float* __restrict__ Wmu,
                                                   const float* __restrict__ bmu,
                                                   const float* __restrict__ Wlv,
                                                   const float* __restrict__ blv,
                                                   float* __restrict__ out_mu,
                                                   float* __restrict__ out_lv,
                                                   float* __restrict__ zbuf) {
    int b = blockIdx.x;
    int tid = threadIdx.x;
    __shared__ float sh[2*HH];
    for (int i = tid; i < HH; i += 256) {
        sh[i]      = hfT[(size_t)i*BB + b];
        sh[HH + i] = hbT[(size_t)i*BB + b];
    }
    __syncthreads();
    const float* W;
    float acc;
    int l;
    if (tid < LL) { l = tid;      W = Wmu + (size_t)l*2*HH; acc = bmu[l]; }
    else          { l = tid - LL; W = Wlv + (size_t)l*2*HH; acc = blv[l]; }
    #pragma unroll 8
    for (int k = 0; k < 2*HH; k++) acc += sh[k]*W[k];
    if (tid < LL) { out_mu[b*LL + l] = acc; zbuf[b*LL + l] = acc; }
    else          { out_lv[b*LL + l] = acc; }
}

// ---------------- decoder init ----------------
__global__ __launch_bounds__(512) void dec_init_kernel(const float* __restrict__ z,
                                                       const float* __restrict__ W,
                                                       const float* __restrict__ bias,
                                                       __half* __restrict__ h0h, __half* __restrict__ h0l,
                                                       __half* __restrict__ h1h, __half* __restrict__ h1l,
                                                       float* __restrict__ h1n,
                                                       float* __restrict__ c0n,
                                                       float* __restrict__ c1T) {
    int b = blockIdx.x;
    int tid = threadIdx.x;
    __shared__ float sz[LL];
    if (tid < LL) sz[tid] = z[b*LL + tid];
    __syncthreads();
    float acc = bias[tid];
    const float* w = W + (size_t)tid*LL;
    #pragma unroll 8
    for (int k = 0; k < LL; k++) acc += sz[k]*w[k];
    __half hh, hl; split2h(acc, hh, hl);
    h0h[(size_t)b*HH + tid] = hh; h0l[(size_t)b*HH + tid] = hl;
    h1h[(size_t)b*HH + tid] = hh; h1l[(size_t)b*HH + tid] = hl;
    h1n[(size_t)b*HH + tid] = acc;
    c0n[(size_t)b*HH + tid] = 0.0f;
    c1T[(size_t)tid*BB + b] = 0.0f;
}

// ================= sgemm_ca (fp32, Ptab only) =================
__global__ __launch_bounds__(256, 2) void sgemm_ca(const float* __restrict__ AT,
                                                   const float* __restrict__ WT,
                                                   const float* __restrict__ bias,
                                                   float* __restrict__ C,
                                                   int M, int N, int K) {
    __shared__ __align__(16) float S[2*4096];
    const int bm = blockIdx.y * 128;
    const int bn = blockIdx.x * 128;
    const int tid = threadIdx.x;
    const int tx = tid % 16;
    const int ty = tid / 16;
    const int NS = K / 16;
    const int ck  = tid >> 5;
    const int co  = (tid & 31) * 4;
    const float* asrc = AT + (size_t)ck*M + bm + co;
    const float* wsrc = WT + (size_t)ck*N + bn + co;
    unsigned sb = smem_u32(S);
    unsigned adst = sb + ((ck*128 + co) << 2);
    unsigned wdst = sb + ((2048 + ck*128 + co) << 2);

    #define PRE_ISSUE(s) { unsigned o_ = ((s)&1)*16384u; size_t ka_ = (size_t)(s)*16*M, kw_ = (size_t)(s)*16*N; \
        CP16(adst + o_, asrc + ka_); CP16(adst + o_ + 4096u, asrc + ka_ + 8*(size_t)M); \
        CP16(wdst + o_, wsrc + kw_); CP16(wdst + o_ + 4096u, wsrc + kw_ + 8*(size_t)N); CP_COMMIT; }

    u64t acc2[4][8];
    #pragma unroll
    for (int p = 0; p < 4; p++)
        #pragma unroll
        for (int j = 0; j < 8; j++) acc2[p][j] = 0ull;

    PRE_ISSUE(0); PRE_ISSUE(1);
    CP_WAIT1; __syncthreads();

    for (int s = 0; s < NS; s++) {
        const float* Bq = S + (s & 1)*4096;
        #pragma unroll
        for (int k = 0; k < 16; k++) {
            ulonglong2 A0 = *(const ulonglong2*)&Bq[k*128 + ty*8];
            ulonglong2 A1 = *(const ulonglong2*)&Bq[k*128 + ty*8 + 4];
            u64t apair[4] = {A0.x, A0.y, A1.x, A1.y};
            float w[8];
            *(float4*)&w[0] = *(const float4*)&Bq[2048 + k*128 + tx*8];
            *(float4*)&w[4] = *(const float4*)&Bq[2048 + k*128 + tx*8 + 4];
            #pragma unroll
            for (int j = 0; j < 8; j++) {
                u64t w2 = pack2(w[j], w[j]);
                #pragma unroll
                for (int p = 0; p < 4; p++) fma2(acc2[p][j], apair[p], w2);
            }
        }
        if (s == NS - 1) break;
        __syncthreads();
        if (s + 2 < NS) { PRE_ISSUE(s+2); CP_WAIT1; }
        else            { CP_WAIT0; }
        __syncthreads();
    }

    float bb[8];
    *(float4*)&bb[0] = *(const float4*)(bias + bn + tx*8);
    *(float4*)&bb[4] = *(const float4*)(bias + bn + tx*8 + 4);
    #pragma unroll
    for (int p = 0; p < 4; p++) {
        float2 v[8];
        #pragma unroll
        for (int j = 0; j < 8; j++) v[j] = unpack2(acc2[p][j]);
        #pragma unroll
        for (int sub = 0; sub < 2; sub++) {
            size_t row = (size_t)(bm + ty*8 + 2*p + sub)*N + bn + tx*8;
            float o[8];
            #pragma unroll
            for (int j = 0; j < 8; j++) o[j] = (sub ? v[j].y : v[j].x) + bb[j];
            *(float4*)&C[row]     = *(float4*)&o[0];
            *(float4*)&C[row + 4] = *(float4*)&o[4];
        }
    }
    #undef PRE_ISSUE
}

// =================================== host launcher ====================================
extern "C" void kernel_launch(void* const* d_in, const int* in_sizes, int n_in,
                              void* d_out, int out_size) {
    const int*   x           = (const int*)  d_in[0];
    const float* emb         = (const float*)d_in[1];
    const float* enc_wih_l0  = (const float*)d_in[2];
    const float* enc_whh_l0  = (const float*)d_in[3];
    const float* enc_b_l0    = (const float*)d_in[4];
    const float* enc_wih_l1  = (const float*)d_in[5];
    const float* enc_whh_l1  = (const float*)d_in[6];
    const float* enc_b_l1    = (const float*)d_in[7];
    const float* fc_mu_w     = (const float*)d_in[8];
    const float* fc_mu_b     = (const float*)d_in[9];
    const float* fc_lv_w     = (const float*)d_in[10];
    const float* fc_lv_b     = (const float*)d_in[11];
    const float* dec_in_w    = (const float*)d_in[12];
    const float* dec_in_b    = (const float*)d_in[13];
    const float* dec_wih     = (const float*)d_in[14];
    const float* dec_whh     = (const float*)d_in[15];
    const float* dec_b       = (const float*)d_in[16];
    const float* dec_out_w   = (const float*)d_in[17];
    const float* dec_out_b   = (const float*)d_in[18];

    float* out       = (float*)d_out;
    float* out_recon = out;
    float* out_mu    = out + (size_t)BB*TT*VV;
    float* out_lv    = out_mu + (size_t)BB*LL;

    float *preF, *preB, *c0fT, *c0bT, *c1fT, *c1bT, *zeros, *zbuf;
    float *y1fT, *y1bT, *dh1n, *dc0, *dc1T, *part0, *part1a, *ptab, *embT, *wtPt;
    __half *zh, *a0h, *a0l, *a1h, *a1l, *y1sfh, *y1sfl, *y1sbh, *y1sbl;
    __half *w0h, *w0l, *w1h, *w1l, *w4h, *w4l, *dh0h, *dh0l, *dh1h, *dh1l;
    cudaGetSymbolAddress((void**)&preF,  g_preF);
    cudaGetSymbolAddress((void**)&preB,  g_preB);
    cudaGetSymbolAddress((void**)&c0fT,  g_c0fT);
    cudaGetSymbolAddress((void**)&c0bT,  g_c0bT);
    cudaGetSymbolAddress((void**)&c1fT,  g_c1fT);
    cudaGetSymbolAddress((void**)&c1bT,  g_c1bT);
    cudaGetSymbolAddress((void**)&zeros, g_zeros);
    cudaGetSymbolAddress((void**)&zbuf,  g_z);
    cudaGetSymbolAddress((void**)&y1fT,  g_y1fT);
    cudaGetSymbolAddress((void**)&y1bT,  g_y1bT);
    cudaGetSymbolAddress((void**)&dh1n,  g_dh1n);
    cudaGetSymbolAddress((void**)&dc0,   g_dc0);
    cudaGetSymbolAddress((void**)&dc1T,  g_dc1T);
    cudaGetSymbolAddress((void**)&part0, g_part0);
    cudaGetSymbolAddress((void**)&part1a,g_part1a);
    cudaGetSymbolAddress((void**)&ptab,  g_ptab);
    cudaGetSymbolAddress((void**)&embT,  g_embT);
    cudaGetSymbolAddress((void**)&wtPt,  g_wt);
    cudaGetSymbolAddress((void**)&zh,    g_zh);
    cudaGetSymbolAddress((void**)&a0h,   g_a0h);  cudaGetSymbolAddress((void**)&a0l, g_a0l);
    cudaGetSymbolAddress((void**)&a1h,   g_a1h);  cudaGetSymbolAddress((void**)&a1l, g_a1l);
    cudaGetSymbolAddress((void**)&y1sfh, g_y1sfh);cudaGetSymbolAddress((void**)&y1sfl, g_y1sfl);
    cudaGetSymbolAddress((void**)&y1sbh, g_y1sbh);cudaGetSymbolAddress((void**)&y1sbl, g_y1sbl);
    cudaGetSymbolAddress((void**)&w0h,   g_w0h);  cudaGetSymbolAddress((void**)&w0l, g_w0l);
    cudaGetSymbolAddress((void**)&w1h,   g_w1h);  cudaGetSymbolAddress((void**)&w1l, g_w1l);
    cudaGetSymbolAddress((void**)&w4h,   g_w4h);  cudaGetSymbolAddress((void**)&w4l, g_w4l);
    cudaGetSymbolAddress((void**)&dh0h,  g_dh0h); cudaGetSymbolAddress((void**)&dh0l, g_dh0l);
    cudaGetSymbolAddress((void**)&dh1h,  g_dh1h); cudaGetSymbolAddress((void**)&dh1l, g_dh1l);

    const size_t WS = (size_t)GG*HH;
    __half* e0fh = w4h;          __half* e0fl = w4l;
    __half* e0bh = w4h + 1*WS;   __half* e0bl = w4l + 1*WS;
    __half* e1fh = w4h + 2*WS;   __half* e1fl = w4l + 2*WS;
    __half* e1bh = w4h + 3*WS;   __half* e1bl = w4l + 3*WS;
    __half* ih1h = w4h + 4*WS;   __half* ih1l = w4l + 4*WS;
    __half* hh0h = w4h + 5*WS;   __half* hh0l = w4l + 5*WS;
    __half* hh1h = w4h + 6*WS;   __half* hh1l = w4l + 6*WS;

    const float* dWih0 = dec_wih;
    const float* dWih1 = dec_wih + WS;
    const float* dWhh0 = dec_whh;
    const float* dWhh1 = dec_whh + WS;
    const float* db0   = dec_b;
    const float* db1   = dec_b + GG;

    const int MMH = 2*(int)HM_STAGE;   // 61440 (pre-GEMM)
    const int GMH = (int)GM_SMEM;      // 40960 (recurrent)
    cudaFuncSetAttribute(mma_hm,      cudaFuncAttributeMaxDynamicSharedMemorySize, MMH);
    cudaFuncSetAttribute(enc_step_hm, cudaFuncAttributeMaxDynamicSharedMemorySize, GMH);
    cudaFuncSetAttribute(dec_part_hm, cudaFuncAttributeMaxDynamicSharedMemorySize, GMH);
    cudaFuncSetAttribute(dec_Y_hm,    cudaFuncAttributeMaxDynamicSharedMemorySize, GMH);
    cudaFuncSetAttribute(dec_Z_hm,    cudaFuncAttributeMaxDynamicSharedMemorySize, GMH);

    // ---- transforms + splits ----
    embsplit2<<<2048, 256>>>(x, emb, a0h, a0l);
    wsplit2<<<2048, 256>>>(enc_wih_l0, w0h, w0l, 2*GG*HH);
    wsplit2<<<4096, 256>>>(enc_wih_l1, w1h, w1l, 2*GG*2*HH);
    wsplit4<<<1024, 256>>>(enc_whh_l0,      e0fh, e0fl);
    wsplit4<<<1024, 256>>>(enc_whh_l0 + WS, e0bh, e0bl);
    wsplit4<<<1024, 256>>>(enc_whh_l1,      e1fh, e1fl);
    wsplit4<<<1024, 256>>>(enc_whh_l1 + WS, e1bh, e1bl);
    wsplit4<<<1024, 256>>>(dWih1, ih1h, ih1l);
    wsplit4<<<1024, 256>>>(dWhh0, hh0h, hh0l);
    wsplit4<<<1024, 256>>>(dWhh1, hh1h, hh1l);
    wt_kernel<<<512, 256>>>(emb, embT, VV, HH);
    wt_kernel<<<1024, 256>>>(dWih0, wtPt, GG, HH);

    // ---- Ptab ----
    sgemm_ca<<<dim3(GG/128, VV/128), 256>>>(embT, wtPt, db0, ptab, VV, GG, HH);

    // ---- encoder layer 0 pre-GEMMs (HMMA) ----
    dim3 hmGrd(GG/64, LDH/128);
    mma_hm<<<hmGrd, 256, MMH>>>(a0h, a0l, w0h, w0l, enc_b_l0,      preF, GG, HH);
    mma_hm<<<hmGrd, 256, MMH>>>(a0h, a0l, w0h + WS, w0l + WS, enc_b_l0 + GG, preB, GG, HH);

    // ---- encoder layer 0 recurrent steps (HMMA, 64x64 tile, 256 blocks) ----
    dim3 stepGrd(GG/64, BB/64, 2);   // (32,4,2) = 256 blocks
    for (int s = 0; s < TT; s++) {
        int tf = s, tb = TT-1-s;
        EStep df = { s ? a1h + (size_t)(tf-1)*BB*1024 : zh,
                     s ? a1l + (size_t)(tf-1)*BB*1024 : zh, s ? 1024 : HH,
                     e0fh, e0fl,
                     preF + (size_t)tf*BB*GG,
                     s ? c0fT : zeros, c0fT, nullptr,
                     a1h + (size_t)tf*BB*1024, a1l + (size_t)tf*BB*1024, 1024 };
        EStep db = { s ? a1h + (size_t)(tb+1)*BB*1024 + 512 : zh,
                     s ? a1l + (size_t)(tb+1)*BB*1024 + 512 : zh, s ? 1024 : HH,
                     e0bh, e0bl,
                     preB + (size_t)tb*BB*GG,
                     s ? c0bT : zeros, c0bT, nullptr,
                     a1h + (size_t)tb*BB*1024 + 512, a1l + (size_t)tb*BB*1024 + 512, 1024 };
        enc_step_hm<<<stepGrd, 256, GMH>>>(df, db);
    }

    // ---- encoder layer 1 pre-GEMMs (HMMA, K=1024) ----
    mma_hm<<<hmGrd, 256, MMH>>>(a1h, a1l, w1h, w1l, enc_b_l1,      preF, GG, 2*HH);
    mma_hm<<<hmGrd, 256, MMH>>>(a1h, a1l, w1h + 2*WS, w1l + 2*WS, enc_b_l1 + GG, preB, GG, 2*HH);

    // ---- encoder layer 1 recurrent steps ----
    for (int s = 0; s < TT; s++) {
        int tf = s, tb = TT-1-s;
        EStep df = { s ? y1sfh + (size_t)(tf-1)*BB*HH : zh,
                     s ? y1sfl + (size_t)(tf-1)*BB*HH : zh, HH,
                     e1fh, e1fl,
                     preF + (size_t)tf*BB*GG,
                     s ? c1fT : zeros, c1fT,
                     (tf == TT-1) ? y1fT : nullptr,
                     y1sfh + (size_t)tf*BB*HH, y1sfl + (size_t)tf*BB*HH, HH };
        EStep db = { s ? y1sbh + (size_t)(tb+1)*BB*HH : zh,
                     s ? y1sbl + (size_t)(tb+1)*BB*HH : zh, HH,
                     e1bh, e1bl,
                     preB + (size_t)tb*BB*GG,
                     s ? c1bT : zeros, c1bT,
                     (tb == 0) ? y1bT : nullptr,
                     y1sbh + (size_t)tb*BB*HH, y1sbl + (size_t)tb*BB*HH, HH };
        enc_step_hm<<<stepGrd, 256, GMH>>>(df, db);
    }

    // ---- heads ----
    head_kernel<<<BB, 256>>>(y1fT, y1bT, fc_mu_w, fc_mu_b, fc_lv_w, fc_lv_b,
                             out_mu, out_lv, zbuf);

    // ---- decoder init ----
    dec_init_kernel<<<BB, 512>>>(zbuf, dec_in_w, dec_in_b,
                                 dh0h, dh0l, dh1h, dh1l, dh1n, dc0, dc1T);
    dim3 partGrd(GG/64, BB/64);
    dec_part_hm<<<partGrd, 256, GMH>>>(dh0h, dh0l, hh0h, hh0l, zeros, part0);
    dec_part_hm<<<partGrd, 256, GMH>>>(dh1h, dh1l, hh1h, hh1l, db1,   part1a);
    cell0_init_kernel<<<BB, 128>>>(ptab, part0, dc0, dh0h, dh0l);

    // ---- autoregressive decode: 2 launches per step ----
    dim3 decGrd(GG/64, BB/64, 2);
    for (int t = 0; t < TT; t++) {
        dec_Y_hm<<<decGrd, 256, GMH>>>(dh0h, dh0l, ih1h, ih1l, part1a, dc1T,
                                       dh1n, dh1h, dh1l, hh0h, hh0l, zeros, part0);
        dec_Z_hm<<<decGrd, 256, GMH>>>(dh1h, dh1l, hh1h, hh1l, db1, part1a,
                                       dh1n, dec_out_w, dec_out_b,
                                       ptab, part0, dc0, dh0h, dh0l, out_recon, t);
    }
}

// round 17
// speedup vs baseline: 1.1657x; 1.1657x over previous
#include <cuda_runtime.h>
#include <cuda_fp16.h>
#include <cstdint>
#include <math.h>

#define TT 128
#define BB 256
#define HH 512
#define GG 2048
#define VV 128
#define LL 128
#define LDH (TT*BB)

typedef unsigned long long u64t;

__device__ __forceinline__ u64t pack2(float x, float y) {
    u64t r; asm("mov.b64 %0, {%1, %2};" : "=l"(r) : "f"(x), "f"(y)); return r;
}
__device__ __forceinline__ void fma2(u64t& d, u64t a, u64t b) {
    asm("fma.rn.f32x2 %0, %1, %2, %0;" : "+l"(d) : "l"(a), "l"(b));
}
__device__ __forceinline__ float2 unpack2(u64t v) {
    float2 r; asm("mov.b64 {%0, %1}, %2;" : "=f"(r.x), "=f"(r.y) : "l"(v)); return r;
}
__device__ __forceinline__ unsigned smem_u32(const void* p) {
    return (unsigned)__cvta_generic_to_shared(p);
}
#define CP16(dst, src) asm volatile("cp.async.ca.shared.global [%0], [%1], 16;" :: "r"(dst), "l"((const void*)(src)) : "memory")
#define CP_COMMIT      asm volatile("cp.async.commit_group;" ::: "memory")
#define CP_WAIT1       asm volatile("cp.async.wait_group 1;" ::: "memory")
#define CP_WAIT0       asm volatile("cp.async.wait_group 0;" ::: "memory")

__device__ __forceinline__ float ex2f(float x) { float r; asm("ex2.approx.ftz.f32 %0, %1;" : "=f"(r) : "f"(x)); return r; }
__device__ __forceinline__ float rcpf(float x) { float r; asm("rcp.approx.ftz.f32 %0, %1;" : "=f"(r) : "f"(x)); return r; }
__device__ __forceinline__ float sigf(float v)  { return rcpf(1.0f + ex2f(-1.4426950408889634f*v)); }
__device__ __forceinline__ float tanhf_(float v){ return 2.0f*rcpf(1.0f + ex2f(-2.8853900817779268f*v)) - 1.0f; }

__device__ __forceinline__ void split2h(float v, __half& h, __half& l) {
    h = __float2half(v);
    l = __float2half((v - __half2float(h)) * 2048.0f);
}

// ---------------- device scratch ----------------
__device__ __align__(16) float g_preF [TT*BB*GG];
__device__ __align__(16) float g_preB [TT*BB*GG];
__device__ __align__(16) float g_c0fT [HH*BB];
__device__ __align__(16) float g_c0bT [HH*BB];
__device__ __align__(16) float g_c1fT [HH*BB];
__device__ __align__(16) float g_c1bT [HH*BB];
__device__ __align__(16) float g_zeros[HH*BB];
__device__ __align__(16) float g_z    [BB*LL];
__device__ __align__(16) float g_y1fT [HH*BB];
__device__ __align__(16) float g_y1bT [HH*BB];
__device__ __align__(16) float g_dh1n [BB*HH];
__device__ __align__(16) float g_dc0  [BB*HH];
__device__ __align__(16) float g_dc1T [HH*BB];
__device__ __align__(16) float g_part0 [BB*GG];
__device__ __align__(16) float g_part1a[BB*GG];
__device__ __align__(16) float g_ptab [VV*GG];
__device__ __align__(16) float g_embT [HH*VV];
__device__ __align__(16) float g_wt   [1024*1024];
// fp16 splits
__device__ __align__(16) __half g_zh  [BB*HH];
__device__ __align__(16) __half g_a0h[LDH*HH],    g_a0l[LDH*HH];
__device__ __align__(16) __half g_a1h[LDH*2*HH],  g_a1l[LDH*2*HH];
__device__ __align__(16) __half g_y1sfh[LDH*HH],  g_y1sfl[LDH*HH];
__device__ __align__(16) __half g_y1sbh[LDH*HH],  g_y1sbl[LDH*HH];
__device__ __align__(16) __half g_w0h[2*GG*HH],   g_w0l[2*GG*HH];
__device__ __align__(16) __half g_w1h[2*GG*2*HH], g_w1l[2*GG*2*HH];
__device__ __align__(16) __half g_w4h[7*GG*HH],   g_w4l[7*GG*HH];
__device__ __align__(16) __half g_dh0h[BB*HH], g_dh0l[BB*HH];
__device__ __align__(16) __half g_dh1h[BB*HH], g_dh1l[BB*HH];

// ---------------- transforms ----------------
__global__ void wt_kernel(const float* __restrict__ in, float* __restrict__ out, int N, int K) {
    int total = N*K;
    for (int i = blockIdx.x*blockDim.x + threadIdx.x; i < total; i += gridDim.x*blockDim.x) {
        int n = i % N; int k = i / N;
        out[i] = in[(size_t)n*K + k];
    }
}
__global__ void wsplit2(const float* __restrict__ in, __half* __restrict__ oh,
                        __half* __restrict__ ol, int total) {
    for (int i = blockIdx.x*blockDim.x + threadIdx.x; i < total; i += gridDim.x*blockDim.x) {
        __half h, l; split2h(in[i], h, l);
        oh[i] = h; ol[i] = l;
    }
}
__global__ void wsplit4(const float* __restrict__ in, __half* __restrict__ oh,
                        __half* __restrict__ ol) {
    int total = GG*HH;
    for (int i = blockIdx.x*blockDim.x + threadIdx.x; i < total; i += gridDim.x*blockDim.x) {
        int j = i >> 9, k = i & 511;
        int n = j >> 2, g = j & 3;
        __half h, l; split2h(in[((size_t)(g*HH + n))*HH + k], h, l);
        oh[i] = h; ol[i] = l;
    }
}
__global__ void embsplit2(const int* __restrict__ x, const float* __restrict__ emb,
                          __half* __restrict__ ah, __half* __restrict__ al) {
    int total = LDH*HH;
    for (int i = blockIdx.x*blockDim.x + threadIdx.x; i < total; i += gridDim.x*blockDim.x) {
        int m = i >> 9, k = i & 511;
        int t = m / BB, b = m % BB;
        __half h, l; split2h(emb[x[b*TT + t]*HH + k], h, l);
        ah[i] = h; al[i] = l;
    }
}

// ============ HMMA pre-GEMM (round-14, unchanged) ============
#define HM_STAGE 30720u
#define MMA16816(c, a0,a1,a2,a3, b0,b1) \
  asm volatile("mma.sync.aligned.m16n8k16.row.col.f32.f16.f16.f32 " \
    "{%0,%1,%2,%3}, {%4,%5,%6,%7}, {%8,%9}, {%0,%1,%2,%3};" \
    : "+f"((c)[0]), "+f"((c)[1]), "+f"((c)[2]), "+f"((c)[3]) \
    : "r"(a0),"r"(a1),"r"(a2),"r"(a3),"r"(b0),"r"(b1))

__global__ __launch_bounds__(256, 2) void mma_hm(
    const __half* __restrict__ Ah, const __half* __restrict__ Al,
    const __half* __restrict__ Wh, const __half* __restrict__ Wl,
    const float* __restrict__ bias, float* __restrict__ C, int N, int K) {
    extern __shared__ __align__(16) char HSm[];
    unsigned sb = smem_u32(HSm);
    const int tid = threadIdx.x;
    const int lane = tid & 31;
    const int wid = tid >> 5;
    const int wmB = (wid & 3) * 32;
    const int wnB = (wid >> 2) * 32;
    const int bm = blockIdx.y * 128;
    const int bn = blockIdx.x * 64;
    const int NS = K / 32;

    const __half* Asrc[2] = { Ah + (size_t)bm*K, Al + (size_t)bm*K };
    const __half* Wsrc[2] = { Wh + (size_t)bn*K, Wl + (size_t)bn*K };

    #define HLOAD(s) { unsigned db_ = sb + (unsigned)((s)&1)*HM_STAGE; size_t kb_ = (size_t)(s)*32; \
        _Pragma("unroll") for (int j = 0; j < 4; j++) { \
            int c_ = tid + j*256; int mt_ = c_ >> 9; int rk_ = c_ & 511; \
            int r_ = rk_ >> 2; int o_ = (rk_ & 3) * 8; \
            CP16(db_ + (unsigned)(mt_*10240 + r_*80 + o_*2), Asrc[mt_] + (size_t)r_*K + kb_ + o_); } \
        _Pragma("unroll") for (int j = 0; j < 2; j++) { \
            int c_ = tid + j*256; int mt_ = c_ >> 8; int rk_ = c_ & 255; \
            int r_ = rk_ >> 2; int o_ = (rk_ & 3) * 8; \
            CP16(db_ + (unsigned)(20480 + mt_*5120 + r_*80 + o_*2), Wsrc[mt_] + (size_t)r_*K + kb_ + o_); } \
        CP_COMMIT; }

    float c0[2][4][4], c1[2][4][4];
    #pragma unroll
    for (int mt = 0; mt < 2; mt++)
        #pragma unroll
        for (int nt = 0; nt < 4; nt++)
            #pragma unroll
            for (int q = 0; q < 4; q++) { c0[mt][nt][q] = 0.0f; c1[mt][nt][q] = 0.0f; }

    HLOAD(0); HLOAD(1);
    CP_WAIT1; __syncthreads();

    const int arow = lane >> 2;
    const int acol = (lane & 3) * 2;

    for (int s = 0; s < NS; s++) {
        const char* bufb = HSm + (s & 1)*HM_STAGE;
        #pragma unroll
        for (int kk = 0; kk < 32; kk += 16) {
            uint32_t BH[4][2], BL[4][2];
            #pragma unroll
            for (int nt = 0; nt < 4; nt++) {
                const char* wb = bufb + 20480 + (wnB + nt*8 + arow)*80 + (acol + kk)*2;
                BH[nt][0] = *(const uint32_t*)wb;
                BH[nt][1] = *(const uint32_t*)(wb + 16);
                BL[nt][0] = *(const uint32_t*)(wb + 5120);
                BL[nt][1] = *(const uint32_t*)(wb + 5120 + 16);
            }
            #pragma unroll
            for (int mt = 0; mt < 2; mt++) {
                const char* ab = bufb + (wmB + mt*16 + arow)*80 + (acol + kk)*2;
                uint32_t AH0 = *(const uint32_t*)ab;
                uint32_t AH1 = *(const uint32_t*)(ab + 640);
                uint32_t AH2 = *(const uint32_t*)(ab + 16);
                uint32_t AH3 = *(const uint32_t*)(ab + 640 + 16);
                uint32_t AL0 = *(const uint32_t*)(ab + 10240);
                uint32_t AL1 = *(const uint32_t*)(ab + 10240 + 640);
                uint32_t AL2 = *(const uint32_t*)(ab + 10240 + 16);
                uint32_t AL3 = *(const uint32_t*)(ab + 10240 + 640 + 16);
                #pragma unroll
                for (int nt = 0; nt < 4; nt++) {
                    MMA16816(c0[mt][nt], AH0,AH1,AH2,AH3, BH[nt][0],BH[nt][1]);
                    MMA16816(c1[mt][nt], AH0,AH1,AH2,AH3, BL[nt][0],BL[nt][1]);
                    MMA16816(c1[mt][nt], AL0,AL1,AL2,AL3, BH[nt][0],BH[nt][1]);
                }
            }
        }
        if (s == NS - 1) break;
        __syncthreads();
        if (s + 2 < NS) { HLOAD(s+2); CP_WAIT1; }
        else            { CP_WAIT0; }
        __syncthreads();
    }

    const float INV = 4.8828125e-4f;
    #pragma unroll
    for (int mt = 0; mt < 2; mt++) {
        #pragma unroll
        for (int nt = 0; nt < 4; nt++) {
            int m0 = bm + wmB + mt*16 + arow;
            int n0 = bn + wnB + nt*8 + acol;
            float b0v = bias[n0], b1v = bias[n0+1];
            float2 o0 = make_float2(c0[mt][nt][0] + c1[mt][nt][0]*INV + b0v,
                                    c0[mt][nt][1] + c1[mt][nt][1]*INV + b1v);
            float2 o1 = make_float2(c0[mt][nt][2] + c1[mt][nt][2]*INV + b0v,
                                    c0[mt][nt][3] + c1[mt][nt][3]*INV + b1v);
            *(float2*)&C[(size_t)m0*N + n0]     = o0;
            *(float2*)&C[(size_t)(m0+8)*N + n0] = o1;
        }
    }
    #undef HLOAD
}

// ============ HMMA recurrent core: 64 b x 64 j, K=512 in 8 stages of 64 ============
// Stage layout: Ah 9216 | Al 9216 | Wh 9216 | Wl 9216 = 36864 B (rows padded to 144 B,
// word-stride 36 -> banks 4r+q, conflict-free). 2-deep = 73728 B -> 2 blocks/SM.
#define GM_STAGE 36864u
#define GM_SMEM  (2*GM_STAGE)

__device__ __forceinline__ void hm_core(const __half* __restrict__ Ah,
                                        const __half* __restrict__ Al, int lda,
                                        const __half* __restrict__ Wh,
                                        const __half* __restrict__ Wl,
                                        int bm, int bn, char* HSm, float* Sg) {
    unsigned sb = smem_u32(HSm);
    const int tid = threadIdx.x;
    const int lane = tid & 31;
    const int wid = tid >> 5;
    const int wmB = (wid & 1) * 32;       // 2 m-groups of 32
    const int wnB = (wid >> 1) * 16;      // 4 n-groups of 16
    const __half* Asrc[2] = { Ah + (size_t)bm*lda, Al + (size_t)bm*lda };
    const __half* Wsrc[2] = { Wh + (size_t)bn*HH, Wl + (size_t)bn*HH };

    // 64 rows x 128B per split; 8 chunks of 16B per row; 1024 chunks per operand pair.
    #define GLOAD(s) { unsigned db_ = sb + (unsigned)((s)&1)*GM_STAGE; size_t kb_ = (size_t)(s)*64; \
        _Pragma("unroll") for (int j = 0; j < 4; j++) { \
            int c_ = tid + j*256; int mt_ = c_ >> 9; int rk_ = c_ & 511; \
            int r_ = rk_ >> 3; int o_ = (rk_ & 7) * 8; \
            CP16(db_ + (unsigned)(mt_*9216 + r_*144 + o_*2), Asrc[mt_] + (size_t)r_*lda + kb_ + o_); } \
        _Pragma("unroll") for (int j = 0; j < 4; j++) { \
            int c_ = tid + j*256; int mt_ = c_ >> 9; int rk_ = c_ & 511; \
            int r_ = rk_ >> 3; int o_ = (rk_ & 7) * 8; \
            CP16(db_ + (unsigned)(18432 + mt_*9216 + r_*144 + o_*2), Wsrc[mt_] + (size_t)r_*HH + kb_ + o_); } \
        CP_COMMIT; }

    float c0[2][2][4], c1[2][2][4];
    #pragma unroll
    for (int mt = 0; mt < 2; mt++)
        #pragma unroll
        for (int nt = 0; nt < 2; nt++)
            #pragma unroll
            for (int q = 0; q < 4; q++) { c0[mt][nt][q] = 0.0f; c1[mt][nt][q] = 0.0f; }

    GLOAD(0); GLOAD(1);
    CP_WAIT1; __syncthreads();

    const int arow = lane >> 2;
    const int acol = (lane & 3) * 2;

    for (int s = 0; s < 8; s++) {
        const char* bufb = HSm + (s & 1)*GM_STAGE;
        #pragma unroll
        for (int kk = 0; kk < 64; kk += 16) {
            uint32_t BH[2][2], BL[2][2];
            #pragma unroll
            for (int nt = 0; nt < 2; nt++) {
                const char* wb = bufb + 18432 + (wnB + nt*8 + arow)*144 + (acol + kk)*2;
                BH[nt][0] = *(const uint32_t*)wb;
                BH[nt][1] = *(const uint32_t*)(wb + 16);
                BL[nt][0] = *(const uint32_t*)(wb + 9216);
                BL[nt][1] = *(const uint32_t*)(wb + 9216 + 16);
            }
            #pragma unroll
            for (int mt = 0; mt < 2; mt++) {
                const char* ab = bufb + (wmB + mt*16 + arow)*144 + (acol + kk)*2;
                uint32_t AH0 = *(const uint32_t*)ab;
                uint32_t AH1 = *(const uint32_t*)(ab + 1152);
                uint32_t AH2 = *(const uint32_t*)(ab + 16);
                uint32_t AH3 = *(const uint32_t*)(ab + 1152 + 16);
                uint32_t AL0 = *(const uint32_t*)(ab + 9216);
                uint32_t AL1 = *(const uint32_t*)(ab + 9216 + 1152);
                uint32_t AL2 = *(const uint32_t*)(ab + 9216 + 16);
                uint32_t AL3 = *(const uint32_t*)(ab + 9216 + 1152 + 16);
                #pragma unroll
                for (int nt = 0; nt < 2; nt++) {
                    MMA16816(c0[mt][nt], AH0,AH1,AH2,AH3, BH[nt][0],BH[nt][1]);
                    MMA16816(c1[mt][nt], AH0,AH1,AH2,AH3, BL[nt][0],BL[nt][1]);
                    MMA16816(c1[mt][nt], AL0,AL1,AL2,AL3, BH[nt][0],BH[nt][1]);
                }
            }
        }
        if (s == 7) break;
        __syncthreads();
        if (s + 2 < 8) { GLOAD(s+2); CP_WAIT1; }
        else           { CP_WAIT0; }
        __syncthreads();
    }
    #undef GLOAD

    __syncthreads();
    const float INV = 4.8828125e-4f;
    #pragma unroll
    for (int mt = 0; mt < 2; mt++) {
        #pragma unroll
        for (int nt = 0; nt < 2; nt++) {
            int r0 = wmB + mt*16 + arow;
            int cc = wnB + nt*8 + acol;
            Sg[r0*66 + cc]       = c0[mt][nt][0] + c1[mt][nt][0]*INV;
            Sg[r0*66 + cc + 1]   = c0[mt][nt][1] + c1[mt][nt][1]*INV;
            Sg[(r0+8)*66 + cc]   = c0[mt][nt][2] + c1[mt][nt][2]*INV;
            Sg[(r0+8)*66 + cc+1] = c0[mt][nt][3] + c1[mt][nt][3]*INV;
        }
    }
    __syncthreads();
}

struct EpiT {
    const float* pre;
    const float* cinT; float* coutT;
    float* houtT;
    float* houtN;
    __half *osh, *osl; int olda;
};
__device__ __forceinline__ void hm_lstm_epi(const float* Sg, int bm, int n0, EpiT e) {
    const int tid = threadIdx.x;
    #pragma unroll
    for (int j = 0; j < 4; j++) {
        int idx = tid + j*256;
        int bl = idx >> 4, nn = idx & 15;
        int bg = bm + bl, n = n0 + nn;
        const float* g4 = Sg + bl*66 + nn*4;
        const float* pb = e.pre + (size_t)bg*GG;
        float gi = g4[0] + pb[n];
        float gf = g4[1] + pb[HH + n];
        float gg = g4[2] + pb[2*HH + n];
        float go = g4[3] + pb[3*HH + n];
        float cv = e.cinT[(size_t)n*BB + bg];
        float cn = sigf(gf)*cv + sigf(gi)*tanhf_(gg);
        e.coutT[(size_t)n*BB + bg] = cn;
        float hv = sigf(go)*tanhf_(cn);
        if (e.houtT) e.houtT[(size_t)n*BB + bg] = hv;
        if (e.houtN) e.houtN[(size_t)bg*HH + n] = hv;
        __half hh, hl; split2h(hv, hh, hl);
        e.osh[(size_t)bg*e.olda + n] = hh;
        e.osl[(size_t)bg*e.olda + n] = hl;
    }
}
__device__ __forceinline__ void hm_part_epi(const float* Sg, int bm, int n0,
                                            const float* __restrict__ bias,
                                            float* __restrict__ outp) {
    const int tid = threadIdx.x;
    #pragma unroll
    for (int j = 0; j < 4; j++) {
        int idx = tid + j*256;
        int bl = idx >> 4, nn = idx & 15;
        int bg = bm + bl, n = n0 + nn;
        const float* g4 = Sg + bl*66 + nn*4;
        float* ob = outp + (size_t)bg*GG;
        ob[n]        = g4[0] + bias[n];
        ob[HH + n]   = g4[1] + bias[HH + n];
        ob[2*HH + n] = g4[2] + bias[2*HH + n];
        ob[3*HH + n] = g4[3] + bias[3*HH + n];
    }
}

// ---------------- encoder recurrent step (both dirs via grid.z) ----------------
struct EStep {
    const __half *ah, *al; int alda;
    const __half *wh, *wl;
    const float* pre;
    const float* cinT; float* coutT;
    float* houtT;
    __half *osh, *osl; int olda;
};
__global__ __launch_bounds__(256, 2) void enc_step_hm(EStep D0, EStep D1) {
    extern __shared__ __align__(16) char HSm[];
    EStep d = blockIdx.z ? D1 : D0;
    int bm = blockIdx.y * 64, bn = blockIdx.x * 64;
    float* Sg = (float*)HSm;
    hm_core(d.ah, d.al, d.alda, d.wh, d.wl, bm, bn, HSm, Sg);
    EpiT e = { d.pre, d.cinT, d.coutT, d.houtT, nullptr, d.osh, d.osl, d.olda };
    hm_lstm_epi(Sg, bm, blockIdx.x*16, e);
}

// ---------------- decoder partial (init) ----------------
__global__ __launch_bounds__(256, 2) void dec_part_hm(
    const __half* __restrict__ ah, const __half* __restrict__ al,
    const __half* __restrict__ wh, const __half* __restrict__ wl,
    const float* __restrict__ bias, float* __restrict__ outp) {
    extern __shared__ __align__(16) char HSm[];
    int bm = blockIdx.y * 64, bn = blockIdx.x * 64;
    float* Sg = (float*)HSm;
    hm_core(ah, al, HH, wh, wl, bm, bn, HSm, Sg);
    hm_part_epi(Sg, bm, blockIdx.x*16, bias, outp);
}

// ---------------- decoder phase Y: cell1 (z=0) || part0' (z=1) ----------------
__global__ __launch_bounds__(256, 2) void dec_Y_hm(
    const __half* __restrict__ dh0h, const __half* __restrict__ dh0l,
    const __half* __restrict__ wih1h, const __half* __restrict__ wih1l,
    const float* __restrict__ part1a, float* __restrict__ dc1T,
    float* __restrict__ dh1n, __half* __restrict__ dh1h, __half* __restrict__ dh1l,
    const __half* __restrict__ whh0h, const __half* __restrict__ whh0l,
    const float* __restrict__ zerob, float* __restrict__ part0) {
    extern __shared__ __align__(16) char HSm[];
    int bm = blockIdx.y * 64, bn = blockIdx.x * 64;
    float* Sg = (float*)HSm;
    if (blockIdx.z == 0) {
        hm_core(dh0h, dh0l, HH, wih1h, wih1l, bm, bn, HSm, Sg);
        EpiT e = { part1a, dc1T, dc1T, nullptr, dh1n, dh1h, dh1l, HH };
        hm_lstm_epi(Sg, bm, blockIdx.x*16, e);
    } else {
        hm_core(dh0h, dh0l, HH, whh0h, whh0l, bm, bn, HSm, Sg);
        hm_part_epi(Sg, bm, blockIdx.x*16, zerob, part0);
    }
}

// ---- decoder phase Z: logits+argmax+cell0 (z=0) || part1a' (z=1) ----
__global__ __launch_bounds__(256, 2) void dec_Z_hm(
    const __half* __restrict__ dh1h, const __half* __restrict__ dh1l,
    const __half* __restrict__ whh1h, const __half* __restrict__ whh1l,
    const float* __restrict__ b1, float* __restrict__ part1a,
    const float* __restrict__ dh1n, const float* __restrict__ Wout,
    const float* __restrict__ bout,
    const float* __restrict__ Ptab, const float* __restrict__ part0,
    float* __restrict__ dc0, __half* __restrict__ dh0h, __half* __restrict__ dh0l,
    float* __restrict__ recon, int t) {
    extern __shared__ __align__(16) char HSm[];
    if (blockIdx.z == 1) {
        int bm = blockIdx.y * 64, bn = blockIdx.x * 64;
        float* Sg = (float*)HSm;
        hm_core(dh1h, dh1l, HH, whh1h, whh1l, bm, bn, HSm, Sg);
        hm_part_epi(Sg, bm, blockIdx.x*16, b1, part1a);
        return;
    }
    // logits role: 128 blocks x 256 threads, 2 batch rows each
    const int tid = threadIdx.x;
    const int bid = blockIdx.y*32 + blockIdx.x;   // 0..127
    const int b0r = bid * 2;
    float* sh = (float*)HSm;           // 2*512
    float* sv = sh + 2*HH;             // 2*128
    int*   si = (int*)(sv + 2*VV);     // 2*128
    ((float4*)sh)[tid] = ((const float4*)(dh1n + (size_t)b0r*HH))[tid];
    __syncthreads();
    const int v = tid & 127;
    const int r = tid >> 7;            // 0 or 1
    const float4* w4 = (const float4*)(Wout + (size_t)v*HH);
    float acc = bout[v];
    const float* s0 = sh + r*HH;
    #pragma unroll 8
    for (int k = 0; k < HH/4; k++) {
        float4 wv = w4[k];
        float4 a4 = *(const float4*)&s0[k*4];
        acc += a4.x*wv.x + a4.y*wv.y + a4.z*wv.z + a4.w*wv.w;
    }
    recon[(size_t)(b0r+r)*TT*VV + (size_t)t*VV + v] = acc;
    sv[r*VV + v] = acc;
    si[r*VV + v] = v;
    __syncthreads();
    for (int s2 = 64; s2 > 0; s2 >>= 1) {
        if (v < s2) {
            float ov = sv[r*VV + v + s2]; int oi = si[r*VV + v + s2];
            if (ov > sv[r*VV + v] || (ov == sv[r*VV + v] && oi < si[r*VV + v])) {
                sv[r*VV + v] = ov; si[r*VV + v] = oi;
            }
        }
        __syncthreads();
    }
    const int tk = si[r*VV];
    const int b = b0r + r;
    const int h0c = v * 4;
    const float* pt = Ptab + (size_t)tk*GG;
    const float* p0 = part0 + (size_t)b*GG;
    float4 pi = *(const float4*)&pt[0*HH + h0c]; float4 qi = *(const float4*)&p0[0*HH + h0c];
    float4 pf = *(const float4*)&pt[1*HH + h0c]; float4 qf = *(const float4*)&p0[1*HH + h0c];
    float4 pg = *(const float4*)&pt[2*HH + h0c]; float4 qg = *(const float4*)&p0[2*HH + h0c];
    float4 po = *(const float4*)&pt[3*HH + h0c]; float4 qo = *(const float4*)&p0[3*HH + h0c];
    float4 c4 = *(const float4*)&dc0[(size_t)b*HH + h0c];
    float gi[4] = {pi.x+qi.x, pi.y+qi.y, pi.z+qi.z, pi.w+qi.w};
    float gf[4] = {pf.x+qf.x, pf.y+qf.y, pf.z+qf.z, pf.w+qf.w};
    float gg[4] = {pg.x+qg.x, pg.y+qg.y, pg.z+qg.z, pg.w+qg.w};
    float go[4] = {po.x+qo.x, po.y+qo.y, po.z+qo.z, po.w+qo.w};
    float cc[4] = {c4.x, c4.y, c4.z, c4.w};
    float co[4];
    #pragma unroll
    for (int jj = 0; jj < 4; jj++) {
        float cn = sigf(gf[jj])*cc[jj] + sigf(gi[jj])*tanhf_(gg[jj]);
        co[jj] = cn;
        float hv = sigf(go[jj])*tanhf_(cn);
        __half hh, hl; split2h(hv, hh, hl);
        dh0h[(size_t)b*HH + h0c + jj] = hh;
        dh0l[(size_t)b*HH + h0c + jj] = hl;
    }
    *(float4*)&dc0[(size_t)b*HH + h0c] = make_float4(co[0], co[1], co[2], co[3]);
}

// ---------------- cell0 at t=0 (token fixed = 1) ----------------
__global__ __launch_bounds__(128) void cell0_init_kernel(const float* __restrict__ Ptab,
                                                         const float* __restrict__ part0,
                                                         float* __restrict__ dc0,
                                                         __half* __restrict__ dh0h,
                                                         __half* __restrict__ dh0l) {
    const int b = blockIdx.x;
    const int h0c = threadIdx.x * 4;
    const float* pt = Ptab + (size_t)1*GG;
    const float* p0 = part0 + (size_t)b*GG;
    float4 pi = *(const float4*)&pt[0*HH + h0c]; float4 qi = *(const float4*)&p0[0*HH + h0c];
    float4 pf = *(const float4*)&pt[1*HH + h0c]; float4 qf = *(const float4*)&p0[1*HH + h0c];
    float4 pg = *(const float4*)&pt[2*HH + h0c]; float4 qg = *(const float4*)&p0[2*HH + h0c];
    float4 po = *(const float4*)&pt[3*HH + h0c]; float4 qo = *(const float4*)&p0[3*HH + h0c];
    float4 c4 = *(const float4*)&dc0[(size_t)b*HH + h0c];
    float gi[4] = {pi.x+qi.x, pi.y+qi.y, pi.z+qi.z, pi.w+qi.w};
    float gf[4] = {pf.x+qf.x, pf.y+qf.y, pf.z+qf.z, pf.w+qf.w};
    float gg[4] = {pg.x+qg.x, pg.y+qg.y, pg.z+qg.z, pg.w+qg.w};
    float go[4] = {po.x+qo.x, po.y+qo.y, po.z+qo.z, po.w+qo.w};
    float cc[4] = {c4.x, c4.y, c4.z, c4.w};
    float co[4];
    #pragma unroll
    for (int j = 0; j < 4; j++) {
        float cn = sigf(gf[j])*cc[j] + sigf(gi[j])*tanhf_(gg[j]);
        co[j] = cn;
        float hv = sigf(go[j])*tanhf_(cn);
        __half hh, hl; split2h(hv, hh, hl);
        dh0h[(size_t)b*HH + h0c + j] = hh;
        dh0l[(size_t)b*HH + h0c + j] = hl;
    }
    *(float4*)&dc0[(size_t)b*HH + h0c] = make_float4(co[0], co[1], co[2], co[3]);
}

// ---------------- mu/logvar heads ([n][BB] inputs) ----------------
__global__ __launch_bounds__(256) void head_kernel(const float* __restrict__ hfT,
                                                   const float* __restrict__ hbT,
                                                   const float* __restrict__ Wmu,
                                                   const float* __restrict__ bmu,
                                                   const float* __restrict__ Wlv,
                                                   const float* __restrict__ blv,
                                                   float* __restrict__ out_mu,
                                                   float* __restrict__ out_lv,
                                                   float* __restrict__ zbuf) {
    int b = blockIdx.x;
    int tid = threadIdx.x;
    __shared__ float sh[2*HH];
    for (int i = tid; i < HH; i += 256) {
        sh[i]      = hfT[(size_t)i*BB + b];
        sh[HH + i] = hbT[(size_t)i*BB + b];
    }
    __syncthreads();
    const float* W;
    float acc;
    int l;
    if (tid < LL) { l = tid;      W = Wmu + (size_t)l*2*HH; acc = bmu[l]; }
    else          { l = tid - LL; W = Wlv + (size_t)l*2*HH; acc = blv[l]; }
    #pragma unroll 8
    for (int k = 0; k < 2*HH; k++) acc += sh[k]*W[k];
    if (tid < LL) { out_mu[b*LL + l] = acc; zbuf[b*LL + l] = acc; }
    else          { out_lv[b*LL + l] = acc; }
}

// ---------------- decoder init ----------------
__global__ __launch_bounds__(512) void dec_init_kernel(const float* __restrict__ z,
                                                       const float* __restrict__ W,
                                                       const float* __restrict__ bias,
                                                       __half* __restrict__ h0h, __half* __restrict__ h0l,
                                                       __half* __restrict__ h1h, __half* __restrict__ h1l,
                                                       float* __restrict__ h1n,
                                                       float* __restrict__ c0n,
                                                       float* __restrict__ c1T) {
    int b = blockIdx.x;
    int tid = threadIdx.x;
    __shared__ float sz[LL];
    if (tid < LL) sz[tid] = z[b*LL + tid];
    __syncthreads();
    float acc = bias[tid];
    const float* w = W + (size_t)tid*LL;
    #pragma unroll 8
    for (int k = 0; k < LL; k++) acc += sz[k]*w[k];
    __half hh, hl; split2h(acc, hh, hl);
    h0h[(size_t)b*HH + tid] = hh; h0l[(size_t)b*HH + tid] = hl;
    h1h[(size_t)b*HH + tid] = hh; h1l[(size_t)b*HH + tid] = hl;
    h1n[(size_t)b*HH + tid] = acc;
    c0n[(size_t)b*HH + tid] = 0.0f;
    c1T[(size_t)tid*BB + b] = 0.0f;
}

// ================= sgemm_ca (fp32, Ptab only) =================
__global__ __launch_bounds__(256, 2) void sgemm_ca(const float* __restrict__ AT,
                                                   const float* __restrict__ WT,
                                                   const float* __restrict__ bias,
                                                   float* __restrict__ C,
                                                   int M, int N, int K) {
    __shared__ __align__(16) float S[2*4096];
    const int bm = blockIdx.y * 128;
    const int bn = blockIdx.x * 128;
    const int tid = threadIdx.x;
    const int tx = tid % 16;
    const int ty = tid / 16;
    const int NS = K / 16;
    const int ck  = tid >> 5;
    const int co  = (tid & 31) * 4;
    const float* asrc = AT + (size_t)ck*M + bm + co;
    const float* wsrc = WT + (size_t)ck*N + bn + co;
    unsigned sb = smem_u32(S);
    unsigned adst = sb + ((ck*128 + co) << 2);
    unsigned wdst = sb + ((2048 + ck*128 + co) << 2);

    #define PRE_ISSUE(s) { unsigned o_ = ((s)&1)*16384u; size_t ka_ = (size_t)(s)*16*M, kw_ = (size_t)(s)*16*N; \
        CP16(adst + o_, asrc + ka_); CP16(adst + o_ + 4096u, asrc + ka_ + 8*(size_t)M); \
        CP16(wdst + o_, wsrc + kw_); CP16(wdst + o_ + 4096u, wsrc + kw_ + 8*(size_t)N); CP_COMMIT; }

    u64t acc2[4][8];
    #pragma unroll
    for (int p = 0; p < 4; p++)
        #pragma unroll
        for (int j = 0; j < 8; j++) acc2[p][j] = 0ull;

    PRE_ISSUE(0); PRE_ISSUE(1);
    CP_WAIT1; __syncthreads();

    for (int s = 0; s < NS; s++) {
        const float* Bq = S + (s & 1)*4096;
        #pragma unroll
        for (int k = 0; k < 16; k++) {
            ulonglong2 A0 = *(const ulonglong2*)&Bq[k*128 + ty*8];
            ulonglong2 A1 = *(const ulonglong2*)&Bq[k*128 + ty*8 + 4];
            u64t apair[4] = {A0.x, A0.y, A1.x, A1.y};
            float w[8];
            *(float4*)&w[0] = *(const float4*)&Bq[2048 + k*128 + tx*8];
            *(float4*)&w[4] = *(const float4*)&Bq[2048 + k*128 + tx*8 + 4];
            #pragma unroll
            for (int j = 0; j < 8; j++) {
                u64t w2 = pack2(w[j], w[j]);
                #pragma unroll
                for (int p = 0; p < 4; p++) fma2(acc2[p][j], apair[p], w2);
            }
        }
        if (s == NS - 1) break;
        __syncthreads();
        if (s + 2 < NS) { PRE_ISSUE(s+2); CP_WAIT1; }
        else            { CP_WAIT0; }
        __syncthreads();
    }

    float bb[8];
    *(float4*)&bb[0] = *(const float4*)(bias + bn + tx*8);
    *(float4*)&bb[4] = *(const float4*)(bias + bn + tx*8 + 4);
    #pragma unroll
    for (int p = 0; p < 4; p++) {
        float2 v[8];
        #pragma unroll
        for (int j = 0; j < 8; j++) v[j] = unpack2(acc2[p][j]);
        #pragma unroll
        for (int sub = 0; sub < 2; sub++) {
            size_t row = (size_t)(bm + ty*8 + 2*p + sub)*N + bn + tx*8;
            float o[8];
            #pragma unroll
            for (int j = 0; j < 8; j++) o[j] = (sub ? v[j].y : v[j].x) + bb[j];
            *(float4*)&C[row]     = *(float4*)&o[0];
            *(float4*)&C[row + 4] = *(float4*)&o[4];
        }
    }
    #undef PRE_ISSUE
}

// =================================== host launcher ====================================
extern "C" void kernel_launch(void* const* d_in, const int* in_sizes, int n_in,
                              void* d_out, int out_size) {
    const int*   x           = (const int*)  d_in[0];
    const float* emb         = (const float*)d_in[1];
    const float* enc_wih_l0  = (const float*)d_in[2];
    const float* enc_whh_l0  = (const float*)d_in[3];
    const float* enc_b_l0    = (const float*)d_in[4];
    const float* enc_wih_l1  = (const float*)d_in[5];
    const float* enc_whh_l1  = (const float*)d_in[6];
    const float* enc_b_l1    = (const float*)d_in[7];
    const float* fc_mu_w     = (const float*)d_in[8];
    const float* fc_mu_b     = (const float*)d_in[9];
    const float* fc_lv_w     = (const float*)d_in[10];
    const float* fc_lv_b     = (const float*)d_in[11];
    const float* dec_in_w    = (const float*)d_in[12];
    const float* dec_in_b    = (const float*)d_in[13];
    const float* dec_wih     = (const float*)d_in[14];
    const float* dec_whh     = (const float*)d_in[15];
    const float* dec_b       = (const float*)d_in[16];
    const float* dec_out_w   = (const float*)d_in[17];
    const float* dec_out_b   = (const float*)d_in[18];

    float* out       = (float*)d_out;
    float* out_recon = out;
    float* out_mu    = out + (size_t)BB*TT*VV;
    float* out_lv    = out_mu + (size_t)BB*LL;

    float *preF, *preB, *c0fT, *c0bT, *c1fT, *c1bT, *zeros, *zbuf;
    float *y1fT, *y1bT, *dh1n, *dc0, *dc1T, *part0, *part1a, *ptab, *embT, *wtPt;
    __half *zh, *a0h, *a0l, *a1h, *a1l, *y1sfh, *y1sfl, *y1sbh, *y1sbl;
    __half *w0h, *w0l, *w1h, *w1l, *w4h, *w4l, *dh0h, *dh0l, *dh1h, *dh1l;
    cudaGetSymbolAddress((void**)&preF,  g_preF);
    cudaGetSymbolAddress((void**)&preB,  g_preB);
    cudaGetSymbolAddress((void**)&c0fT,  g_c0fT);
    cudaGetSymbolAddress((void**)&c0bT,  g_c0bT);
    cudaGetSymbolAddress((void**)&c1fT,  g_c1fT);
    cudaGetSymbolAddress((void**)&c1bT,  g_c1bT);
    cudaGetSymbolAddress((void**)&zeros, g_zeros);
    cudaGetSymbolAddress((void**)&zbuf,  g_z);
    cudaGetSymbolAddress((void**)&y1fT,  g_y1fT);
    cudaGetSymbolAddress((void**)&y1bT,  g_y1bT);
    cudaGetSymbolAddress((void**)&dh1n,  g_dh1n);
    cudaGetSymbolAddress((void**)&dc0,   g_dc0);
    cudaGetSymbolAddress((void**)&dc1T,  g_dc1T);
    cudaGetSymbolAddress((void**)&part0, g_part0);
    cudaGetSymbolAddress((void**)&part1a,g_part1a);
    cudaGetSymbolAddress((void**)&ptab,  g_ptab);
    cudaGetSymbolAddress((void**)&embT,  g_embT);
    cudaGetSymbolAddress((void**)&wtPt,  g_wt);
    cudaGetSymbolAddress((void**)&zh,    g_zh);
    cudaGetSymbolAddress((void**)&a0h,   g_a0h);  cudaGetSymbolAddress((void**)&a0l, g_a0l);
    cudaGetSymbolAddress((void**)&a1h,   g_a1h);  cudaGetSymbolAddress((void**)&a1l, g_a1l);
    cudaGetSymbolAddress((void**)&y1sfh, g_y1sfh);cudaGetSymbolAddress((void**)&y1sfl, g_y1sfl);
    cudaGetSymbolAddress((void**)&y1sbh, g_y1sbh);cudaGetSymbolAddress((void**)&y1sbl, g_y1sbl);
    cudaGetSymbolAddress((void**)&w0h,   g_w0h);  cudaGetSymbolAddress((void**)&w0l, g_w0l);
    cudaGetSymbolAddress((void**)&w1h,   g_w1h);  cudaGetSymbolAddress((void**)&w1l, g_w1l);
    cudaGetSymbolAddress((void**)&w4h,   g_w4h);  cudaGetSymbolAddress((void**)&w4l, g_w4l);
    cudaGetSymbolAddress((void**)&dh0h,  g_dh0h); cudaGetSymbolAddress((void**)&dh0l, g_dh0l);
    cudaGetSymbolAddress((void**)&dh1h,  g_dh1h); cudaGetSymbolAddress((void**)&dh1l, g_dh1l);

    const size_t WS = (size_t)GG*HH;
    __half* e0fh = w4h;          __half* e0fl = w4l;
    __half* e0bh = w4h + 1*WS;   __half* e0bl = w4l + 1*WS;
    __half* e1fh = w4h + 2*WS;   __half* e1fl = w4l + 2*WS;
    __half* e1bh = w4h + 3*WS;   __half* e1bl = w4l + 3*WS;
    __half* ih1h = w4h + 4*WS;   __half* ih1l = w4l + 4*WS;
    __half* hh0h = w4h + 5*WS;   __half* hh0l = w4l + 5*WS;
    __half* hh1h = w4h + 6*WS;   __half* hh1l = w4l + 6*WS;

    const float* dWih0 = dec_wih;
    const float* dWih1 = dec_wih + WS;
    const float* dWhh0 = dec_whh;
    const float* dWhh1 = dec_whh + WS;
    const float* db0   = dec_b;
    const float* db1   = dec_b + GG;

    const int MMH = 2*(int)HM_STAGE;   // 61440 (pre-GEMM)
    const int GMH = (int)GM_SMEM;      // 73728 (recurrent, 8-stage K64)
    cudaFuncSetAttribute(mma_hm,      cudaFuncAttributeMaxDynamicSharedMemorySize, MMH);
    cudaFuncSetAttribute(enc_step_hm, cudaFuncAttributeMaxDynamicSharedMemorySize, GMH);
    cudaFuncSetAttribute(dec_part_hm, cudaFuncAttributeMaxDynamicSharedMemorySize, GMH);
    cudaFuncSetAttribute(dec_Y_hm,    cudaFuncAttributeMaxDynamicSharedMemorySize, GMH);
    cudaFuncSetAttribute(dec_Z_hm,    cudaFuncAttributeMaxDynamicSharedMemorySize, GMH);

    // ---- transforms + splits ----
    embsplit2<<<2048, 256>>>(x, emb, a0h, a0l);
    wsplit2<<<2048, 256>>>(enc_wih_l0, w0h, w0l, 2*GG*HH);
    wsplit2<<<4096, 256>>>(enc_wih_l1, w1h, w1l, 2*GG*2*HH);
    wsplit4<<<1024, 256>>>(enc_whh_l0,      e0fh, e0fl);
    wsplit4<<<1024, 256>>>(enc_whh_l0 + WS, e0bh, e0bl);
    wsplit4<<<1024, 256>>>(enc_whh_l1,      e1fh, e1fl);
    wsplit4<<<1024, 256>>>(enc_whh_l1 + WS, e1bh, e1bl);
    wsplit4<<<1024, 256>>>(dWih1, ih1h, ih1l);
    wsplit4<<<1024, 256>>>(dWhh0, hh0h, hh0l);
    wsplit4<<<1024, 256>>>(dWhh1, hh1h, hh1l);
    wt_kernel<<<512, 256>>>(emb, embT, VV, HH);
    wt_kernel<<<1024, 256>>>(dWih0, wtPt, GG, HH);

    // ---- Ptab ----
    sgemm_ca<<<dim3(GG/128, VV/128), 256>>>(embT, wtPt, db0, ptab, VV, GG, HH);

    // ---- encoder layer 0 pre-GEMMs (HMMA) ----
    dim3 hmGrd(GG/64, LDH/128);
    mma_hm<<<hmGrd, 256, MMH>>>(a0h, a0l, w0h, w0l, enc_b_l0,      preF, GG, HH);
    mma_hm<<<hmGrd, 256, MMH>>>(a0h, a0l, w0h + WS, w0l + WS, enc_b_l0 + GG, preB, GG, HH);

    // ---- encoder layer 0 recurrent steps (HMMA, 64x64 tile, 8-stage) ----
    dim3 stepGrd(GG/64, BB/64, 2);   // (32,4,2) = 256 blocks
    for (int s = 0; s < TT; s++) {
        int tf = s, tb = TT-1-s;
        EStep df = { s ? a1h + (size_t)(tf-1)*BB*1024 : zh,
                     s ? a1l + (size_t)(tf-1)*BB*1024 : zh, s ? 1024 : HH,
                     e0fh, e0fl,
                     preF + (size_t)tf*BB*GG,
                     s ? c0fT : zeros, c0fT, nullptr,
                     a1h + (size_t)tf*BB*1024, a1l + (size_t)tf*BB*1024, 1024 };
        EStep db = { s ? a1h + (size_t)(tb+1)*BB*1024 + 512 : zh,
                     s ? a1l + (size_t)(tb+1)*BB*1024 + 512 : zh, s ? 1024 : HH,
                     e0bh, e0bl,
                     preB + (size_t)tb*BB*GG,
                     s ? c0bT : zeros, c0bT, nullptr,
                     a1h + (size_t)tb*BB*1024 + 512, a1l + (size_t)tb*BB*1024 + 512, 1024 };
        enc_step_hm<<<stepGrd, 256, GMH>>>(df, db);
    }

    // ---- encoder layer 1 pre-GEMMs (HMMA, K=1024) ----
    mma_hm<<<hmGrd, 256, MMH>>>(a1h, a1l, w1h, w1l, enc_b_l1,      preF, GG, 2*HH);
    mma_hm<<<hmGrd, 256, MMH>>>(a1h, a1l, w1h + 2*WS, w1l + 2*WS, enc_b_l1 + GG, preB, GG, 2*HH);

    // ---- encoder layer 1 recurrent steps ----
    for (int s = 0; s < TT; s++) {
        int tf = s, tb = TT-1-s;
        EStep df = { s ? y1sfh + (size_t)(tf-1)*BB*HH : zh,
                     s ? y1sfl + (size_t)(tf-1)*BB*HH : zh, HH,
                     e1fh, e1fl,
                     preF + (size_t)tf*BB*GG,
                     s ? c1fT : zeros, c1fT,
                     (tf == TT-1) ? y1fT : nullptr,
                     y1sfh + (size_t)tf*BB*HH, y1sfl + (size_t)tf*BB*HH, HH };
        EStep db = { s ? y1sbh + (size_t)(tb+1)*BB*HH : zh,
                     s ? y1sbl + (size_t)(tb+1)*BB*HH : zh, HH,
                     e1bh, e1bl,
                     preB + (size_t)tb*BB*GG,
                     s ? c1bT : zeros, c1bT,
                     (tb == 0) ? y1bT : nullptr,
                     y1sbh + (size_t)tb*BB*HH, y1sbl + (size_t)tb*BB*HH, HH };
        enc_step_hm<<<stepGrd, 256, GMH>>>(df, db);
    }

    // ---- heads ----
    head_kernel<<<BB, 256>>>(y1fT, y1bT, fc_mu_w, fc_mu_b, fc_lv_w, fc_lv_b,
                             out_mu, out_lv, zbuf);

    // ---- decoder init ----
    dec_init_kernel<<<BB, 512>>>(zbuf, dec_in_w, dec_in_b,
                                 dh0h, dh0l, dh1h, dh1l, dh1n, dc0, dc1T);
    dim3 partGrd(GG/64, BB/64);
    dec_part_hm<<<partGrd, 256, GMH>>>(dh0h, dh0l, hh0h, hh0l, zeros, part0);
    dec_part_hm<<<partGrd, 256, GMH>>>(dh1h, dh1l, hh1h, hh1l, db1,   part1a);
    cell0_init_kernel<<<BB, 128>>>(ptab, part0, dc0, dh0h, dh0l);

    // ---- autoregressive decode: 2 launches per step ----
    dim3 decGrd(GG/64, BB/64, 2);
    for (int t = 0; t < TT; t++) {
        dec_Y_hm<<<decGrd, 256, GMH>>>(dh0h, dh0l, ih1h, ih1l, part1a, dc1T,
                                       dh1n, dh1h, dh1l, hh0h, hh0l, zeros, part0);
        dec_Z_hm<<<decGrd, 256, GMH>>>(dh1h, dh1l, hh1h, hh1l, db1, part1a,
                                       dh1n, dec_out_w, dec_out_b,
                                       ptab, part0, dc0, dh0h, dh0l, out_recon, t);
    }
}